// round 9
// baseline (speedup 1.0000x reference)
#include <cuda_runtime.h>
#include <cstdint>

#define CRF_B 512
#define CRF_S 512
#define CRF_T 64

// Per-batch partial results + completion ticket (device scratch; no allocs).
__device__ float    g_dpart[CRF_B];
__device__ float    g_npart[CRF_B];
__device__ unsigned g_ticket;   // zero-init; last CTA resets it each run

typedef unsigned long long u64;

// ---- packed f32x2 helpers (sm_100+ PTX) ----
__device__ __forceinline__ u64 ffma2(u64 a, u64 b, u64 c) {
    u64 d;
    asm("fma.rn.f32x2 %0, %1, %2, %3;" : "=l"(d) : "l"(a), "l"(b), "l"(c));
    return d;
}
__device__ __forceinline__ u64 fadd2(u64 a, u64 b) {
    u64 d;
    asm("add.rn.f32x2 %0, %1, %2;" : "=l"(d) : "l"(a), "l"(b));
    return d;
}
__device__ __forceinline__ u64 pack2(float x, float y) {
    u64 d;
    asm("mov.b64 %0, {%1, %2};" : "=l"(d) : "f"(x), "f"(y));
    return d;
}
__device__ __forceinline__ float2 unpack2(u64 a) {
    float2 r;
    asm("mov.b64 {%0, %1}, %2;" : "=f"(r.x), "=f"(r.y) : "l"(a));
    return r;
}

// Warp-uniform layout detection (ballot => uniform, no global state).
__device__ __forceinline__ int detect_mshift(const void* mask, int l) {
    const unsigned* mw = (const unsigned*)mask;
    unsigned bad = ((mw[l] | mw[l + 32]) & 0xFFFFFF00u) ? 1u : 0u;
    return __ballot_sync(0xffffffffu, bad) ? 0 : 2;   // u8 : i32
}
__device__ __forceinline__ int detect_tshift(const void* tags, int l) {
    const unsigned* tw = (const unsigned*)tags;
    unsigned odd = tw[2 * l + 1] ? 1u : 0u;
    return __ballot_sync(0xffffffffu, odd) ? 0 : 1;   // i32 : i64
}

// ============================================================================
// Single fused kernel: 128 blocks x 160 threads.
//   Warps 0-3: forward recurrence (denominator), batch = 4*blockIdx.x + w.
//   Warp 4:    numerator (gold-path) for the block's 4 batches.
//   Last CTA to finish: deterministic final reduction.
//
// Forward, i-packed scheme: lane l owns states j0=2l, j1=2l+1, stores its
// pair packed {p_j0,p_j1} (1 STS.64); GEMV = 16 broadcast LDS.128 + 64 FFMA2
// in EIGHT depth-8 chains (R9: halves the dependent-FFMA latency vs 4x16).
// Lazy power-of-2 renorm: scale computed AFTER the store (off the next LDS
// path), folded into the next applied step's e-factor once (apply-and-clear).
// Prefetch uses running pointers (no per-step clamp/IMAD); last 5 steps peeled.
// ============================================================================
__global__ void __launch_bounds__(160, 1) crf_main(
    const float* __restrict__ logits,
    const void* __restrict__ tagsv,
    const void* __restrict__ maskv,
    const float* __restrict__ trans,
    const float* __restrict__ startT,
    const float* __restrict__ endT,
    float* __restrict__ out)
{
    __shared__ __align__(16) u64 psm[4][2][32];   // packed {p_2l, p_2l+1}
    __shared__ float rbuf[256];
    __shared__ int   do_red;

    const int tid = threadIdx.x;
    const int w   = tid >> 5;
    const int l   = tid & 31;

    const int msh = detect_mshift(maskv, l);

    if (w == 4) {
        // ---------------- Numerator warp ----------------
        const int tsh = detect_tshift(tagsv, l);
        const int*           tg  = (const int*)tagsv;
        const unsigned char* mkp = (const unsigned char*)maskv;

        for (int q = 0; q < 4; q++) {
            const int    b  = blockIdx.x * 4 + q;
            const float* lg = logits + (size_t)b * (CRF_S * CRF_T);
            const size_t eb = (size_t)b * CRF_S;

            float acc = 0.0f;
            int   cnt = 0;
            for (int s = l; s < CRF_S; s += 32) {
                const int  t = tg[(eb + s) << tsh];
                const bool m = (mkp[(eb + s) << msh] != 0);
                if (m) {
                    cnt++;
                    if (s < CRF_S - 1) acc += lg[(size_t)s * CRF_T + t];
                    if (s >= 1)        acc += trans[tg[(eb + s - 1) << tsh] * CRF_T + t];
                }
            }
#pragma unroll
            for (int o = 16; o; o >>= 1) {
                acc += __shfl_xor_sync(0xffffffffu, acc, o);
                cnt += __shfl_xor_sync(0xffffffffu, cnt, o);
            }
            if (l == 0) {
                acc += startT[tg[eb << tsh]];
                const int lt = tg[(eb + cnt - 1) << tsh];
                acc += endT[lt];
                if (mkp[(eb + CRF_S - 1) << msh]) acc += lg[(size_t)(CRF_S - 1) * CRF_T + lt];
                g_npart[b] = acc;
            }
        }
    } else {
        // ---------------- Forward warp ----------------
        const int b  = blockIdx.x * 4 + w;
        const int j0 = 2 * l;

        // E pairs along i for this lane's two columns j0, j0+1.
        u64 EA[32], EB[32];
#pragma unroll
        for (int k = 0; k < 32; k++) {
            const float* r0 = trans + (size_t)(2 * k)     * CRF_T + j0;
            const float* r1 = trans + (size_t)(2 * k + 1) * CRF_T + j0;
            EA[k] = pack2(__expf(r0[0]), __expf(r1[0]));
            EB[k] = pack2(__expf(r0[1]), __expf(r1[1]));
        }

        const float*         lg = logits + (size_t)b * (CRF_S * CRF_T);
        const unsigned char* mk = (const unsigned char*)maskv + (((size_t)b * CRF_S) << msh);
        const size_t mstride = (size_t)1 << msh;

        // init: alpha0 = start + logits[:,0,:]; exp-domain with offset C.
        float2 l0 = ((const float2*)lg)[l];
        float a0 = startT[j0]     + l0.x;
        float a1 = startT[j0 + 1] + l0.y;
        float mx = fmaxf(a0, a1);
#pragma unroll
        for (int o = 16; o; o >>= 1) mx = fmaxf(mx, __shfl_xor_sync(0xffffffffu, mx, o));
        float C  = mx;
        float p0 = __expf(a0 - mx);
        float p1 = __expf(a1 - mx);
        psm[w][0][l] = pack2(p0, p1);

        // FIFO prime: e = exp(row 1); f2..f4 = rows 2..4.
        float2 f1 = ((const float2*)(lg + 1 * CRF_T))[l];
        float2 f2 = ((const float2*)(lg + 2 * CRF_T))[l];
        float2 f3 = ((const float2*)(lg + 3 * CRF_T))[l];
        float2 f4 = ((const float2*)(lg + 4 * CRF_T))[l];
        unsigned char m2 = mk[2 * mstride];
        unsigned char m3 = mk[3 * mstride];
        unsigned char m4 = mk[4 * mstride];
        float e0 = __expf(f1.x);
        float e1 = __expf(f1.y);
        unsigned char cm = mk[1 * mstride];

        float ps = 1.0f;   // pending power-of-2 scale (applied ONCE, cleared)
        float pc = 0.0f;   // matching C delta
        __syncwarp();

        // One recurrence step. pfr/pmr: row s+4 pointers; doload const-folds.
        auto step = [&](int s, const u64* src, u64* dst,
                        const float* pfr, const unsigned char* pmr, bool doload) {
            // Pre-scaled e factors (known at step entry; schedules early).
            const float es0 = e0 * ps;
            const float es1 = e1 * ps;

            // GEMV: 16 broadcast LDS.128; 64 FFMA2 in 8 depth-8 chains.
            const ulonglong2* q2p = (const ulonglong2*)src;
            u64 aA[4] = {0ull, 0ull, 0ull, 0ull};
            u64 aB[4] = {0ull, 0ull, 0ull, 0ull};
#pragma unroll
            for (int m = 0; m < 16; m++) {
                ulonglong2 q = q2p[m];
                const int c = m & 3;
                aA[c] = ffma2(EA[2 * m],     q.x, aA[c]);
                aB[c] = ffma2(EB[2 * m],     q.x, aB[c]);
                aA[c] = ffma2(EA[2 * m + 1], q.y, aA[c]);
                aB[c] = ffma2(EB[2 * m + 1], q.y, aB[c]);
            }

            // FIFO rotate + pointer-strided prefetch (no address IMADs).
            const float2 head      = f2;
            const unsigned char mh = m2;
            f2 = f3; m2 = m3;
            f3 = f4; m3 = m4;
            if (doload) {
                f4 = ((const float2*)pfr)[l];
                m4 = *pmr;
            }
            const float ne0 = __expf(head.x);
            const float ne1 = __expf(head.y);

            u64 tA = fadd2(fadd2(aA[0], aA[1]), fadd2(aA[2], aA[3]));
            u64 tB = fadd2(fadd2(aB[0], aB[1]), fadd2(aB[2], aB[3]));
            float2 sA = unpack2(tA);
            float2 sB = unpack2(tB);
            const float pn0 = (sA.x + sA.y) * es0;
            const float pn1 = (sB.x + sB.y) * es1;
            if (cm) {                     // mask: keep old alpha if 0
                p0 = pn0; p1 = pn1; C += pc;
                ps = 1.0f; pc = 0.0f;     // apply-and-clear
            }
            dst[l] = pack2(p0, p1);
            __syncwarp();

            // Refresh pending scale every 4 steps, AFTER the store (off the
            // next step's LDS path). Exact power-of-2, lane-0 exponent.
            if ((s & 3) == 0) {
                int ex = (__float_as_int(p0) >> 23) & 255;
                ex = __shfl_sync(0xffffffffu, ex, 0);
                ps = __int_as_float((254 - ex) << 23);   // 2^(127-ex)
                pc = (float)(ex - 127) * 0.6931471805599453f;
            }
            e0 = ne0; e1 = ne1; cm = mh;
        };

        // Main: s = 1..506 in pairs; prefetch row s+4 (max 510). Then peeled
        // tail s = 507..511 (507 loads row 511; rest drain the FIFO).
        const float*         prow = lg + 5 * CRF_T;
        const unsigned char* pmr  = mk + 5 * mstride;
        for (int s = 1; s <= 505; s += 2) {
            step(s,     psm[w][0], psm[w][1], prow, pmr, true);
            prow += CRF_T; pmr += mstride;
            step(s + 1, psm[w][1], psm[w][0], prow, pmr, true);
            prow += CRF_T; pmr += mstride;
        }
        step(507, psm[w][0], psm[w][1], prow, pmr, true);   // row 511
        step(508, psm[w][1], psm[w][0], prow, pmr, false);
        step(509, psm[w][0], psm[w][1], prow, pmr, false);
        step(510, psm[w][1], psm[w][0], prow, pmr, false);
        step(511, psm[w][0], psm[w][1], prow, pmr, false);

        // denom = C + log(sum_j p_j * exp(end_j))
        float v = p0 * __expf(endT[j0]) + p1 * __expf(endT[j0 + 1]);
#pragma unroll
        for (int o = 16; o; o >>= 1) v += __shfl_xor_sync(0xffffffffu, v, o);
        if (l == 0) g_dpart[b] = C + logf(v);
    }

    // ---- last CTA performs the final deterministic reduction ----
    __syncthreads();
    if (tid == 0) {
        __threadfence();
        unsigned t = atomicAdd(&g_ticket, 1u);
        do_red = (t == gridDim.x - 1);
    }
    __syncthreads();
    if (do_red) {
        __threadfence();
        float a = 0.0f;
        for (int i = tid; i < CRF_B; i += 160)     // fixed order per thread
            a += g_npart[i] - g_dpart[i];
        rbuf[tid] = a;
        if (tid < 96) rbuf[160 + tid] = 0.0f;
        __syncthreads();
        for (int o = 128; o; o >>= 1) {
            if (tid < o) rbuf[tid] += rbuf[tid + o];
            __syncthreads();
        }
        if (tid == 0) { out[0] = rbuf[0]; g_ticket = 0u; }
    }
}

extern "C" void kernel_launch(void* const* d_in, const int* in_sizes, int n_in,
                              void* d_out, int out_size)
{
    const float* logits = (const float*)d_in[0];
    const void*  tags   = d_in[1];
    const void*  mask   = d_in[2];
    const float* trans  = (const float*)d_in[3];
    const float* startT = (const float*)d_in[4];
    const float* endT   = (const float*)d_in[5];
    float*       out    = (float*)d_out;

    crf_main<<<CRF_B / 4, 160>>>(logits, tags, mask, trans, startT, endT, out);
}

// round 12
// speedup vs baseline: 1.4239x; 1.4239x over previous
#include <cuda_runtime.h>
#include <cstdint>

#define CRF_B 512
#define CRF_S 512
#define CRF_T 64

// Per-batch partial results + completion ticket (device scratch; no allocs).
__device__ float    g_dpart[CRF_B];
__device__ float    g_npart[CRF_B];
__device__ unsigned g_ticket;   // zero-init; last CTA resets it each run

typedef unsigned long long u64;

// ---- packed f32x2 helpers (sm_100+ PTX) ----
__device__ __forceinline__ u64 ffma2(u64 a, u64 b, u64 c) {
    u64 d;
    asm("fma.rn.f32x2 %0, %1, %2, %3;" : "=l"(d) : "l"(a), "l"(b), "l"(c));
    return d;
}
__device__ __forceinline__ u64 fadd2(u64 a, u64 b) {
    u64 d;
    asm("add.rn.f32x2 %0, %1, %2;" : "=l"(d) : "l"(a), "l"(b));
    return d;
}
__device__ __forceinline__ u64 pack2(float x, float y) {
    u64 d;
    asm("mov.b64 %0, {%1, %2};" : "=l"(d) : "f"(x), "f"(y));
    return d;
}
__device__ __forceinline__ float2 unpack2(u64 a) {
    float2 r;
    asm("mov.b64 {%0, %1}, %2;" : "=f"(r.x), "=f"(r.y) : "l"(a));
    return r;
}

// Warp-uniform layout detection (ballot => uniform, no global state).
__device__ __forceinline__ int detect_mshift(const void* mask, int l) {
    const unsigned* mw = (const unsigned*)mask;
    unsigned bad = ((mw[l] | mw[l + 32]) & 0xFFFFFF00u) ? 1u : 0u;
    return __ballot_sync(0xffffffffu, bad) ? 0 : 2;   // u8 : i32
}
__device__ __forceinline__ int detect_tshift(const void* tags, int l) {
    const unsigned* tw = (const unsigned*)tags;
    unsigned odd = tw[2 * l + 1] ? 1u : 0u;
    return __ballot_sync(0xffffffffu, odd) ? 0 : 1;   // i32 : i64
}

// ============================================================================
// Single fused kernel: 128 blocks x 160 threads.  (R10 = R8 + ONE change:
// accumulator chains 4x16 -> 8x8, straight-line scalars. Everything else is
// the proven R8 body: eager 1-shfl renorm, clamped prefetch, 2x step bodies.)
//   Warps 0-3: forward recurrence (denominator), batch = 4*blockIdx.x + w.
//   Warp 4:    numerator (gold-path) for the block's 4 batches.
//   Last CTA to finish: deterministic final reduction.
// ============================================================================
__global__ void __launch_bounds__(160, 1) crf_main(
    const float* __restrict__ logits,
    const void* __restrict__ tagsv,
    const void* __restrict__ maskv,
    const float* __restrict__ trans,
    const float* __restrict__ startT,
    const float* __restrict__ endT,
    float* __restrict__ out)
{
    __shared__ __align__(16) u64 psm[4][2][32];   // packed {p_2l, p_2l+1}
    __shared__ float rbuf[256];
    __shared__ int   do_red;

    const int tid = threadIdx.x;
    const int w   = tid >> 5;
    const int l   = tid & 31;

    const int msh = detect_mshift(maskv, l);

    if (w == 4) {
        // ---------------- Numerator warp ----------------
        const int tsh = detect_tshift(tagsv, l);
        const int*           tg  = (const int*)tagsv;
        const unsigned char* mkp = (const unsigned char*)maskv;

        for (int q = 0; q < 4; q++) {
            const int    b  = blockIdx.x * 4 + q;
            const float* lg = logits + (size_t)b * (CRF_S * CRF_T);
            const size_t eb = (size_t)b * CRF_S;

            float acc = 0.0f;
            int   cnt = 0;
            for (int s = l; s < CRF_S; s += 32) {
                const int  t = tg[(eb + s) << tsh];
                const bool m = (mkp[(eb + s) << msh] != 0);
                if (m) {
                    cnt++;
                    if (s < CRF_S - 1) acc += lg[(size_t)s * CRF_T + t];
                    if (s >= 1)        acc += trans[tg[(eb + s - 1) << tsh] * CRF_T + t];
                }
            }
#pragma unroll
            for (int o = 16; o; o >>= 1) {
                acc += __shfl_xor_sync(0xffffffffu, acc, o);
                cnt += __shfl_xor_sync(0xffffffffu, cnt, o);
            }
            if (l == 0) {
                acc += startT[tg[eb << tsh]];
                const int lt = tg[(eb + cnt - 1) << tsh];
                acc += endT[lt];
                if (mkp[(eb + CRF_S - 1) << msh]) acc += lg[(size_t)(CRF_S - 1) * CRF_T + lt];
                g_npart[b] = acc;
            }
        }
    } else {
        // ---------------- Forward warp ----------------
        const int b  = blockIdx.x * 4 + w;
        const int j0 = 2 * l;

        // E pairs along i for this lane's two columns j0, j0+1.
        u64 EA[32], EB[32];
#pragma unroll
        for (int k = 0; k < 32; k++) {
            const float* r0 = trans + (size_t)(2 * k)     * CRF_T + j0;
            const float* r1 = trans + (size_t)(2 * k + 1) * CRF_T + j0;
            EA[k] = pack2(__expf(r0[0]), __expf(r1[0]));
            EB[k] = pack2(__expf(r0[1]), __expf(r1[1]));
        }

        const float*         lg = logits + (size_t)b * (CRF_S * CRF_T);
        const unsigned char* mk = (const unsigned char*)maskv + (((size_t)b * CRF_S) << msh);

        // init: alpha0 = start + logits[:,0,:]; exp-domain with offset C.
        float2 l0 = ((const float2*)lg)[l];
        float a0 = startT[j0]     + l0.x;
        float a1 = startT[j0 + 1] + l0.y;
        float mx = fmaxf(a0, a1);
#pragma unroll
        for (int o = 16; o; o >>= 1) mx = fmaxf(mx, __shfl_xor_sync(0xffffffffu, mx, o));
        float C  = mx;
        float p0 = __expf(a0 - mx);
        float p1 = __expf(a1 - mx);
        psm[w][0][l] = pack2(p0, p1);

        // prologue: 4-deep logits/mask register FIFO + current-step exp.
        float2 f1 = ((const float2*)(lg + 1 * CRF_T))[l];
        float2 f2 = ((const float2*)(lg + 2 * CRF_T))[l];
        float2 f3 = ((const float2*)(lg + 3 * CRF_T))[l];
        float2 f4 = ((const float2*)(lg + 4 * CRF_T))[l];
        float2 f5 = ((const float2*)(lg + 5 * CRF_T))[l];
        unsigned char m2 = mk[(size_t)2 << msh];
        unsigned char m3 = mk[(size_t)3 << msh];
        unsigned char m4 = mk[(size_t)4 << msh];
        unsigned char m5 = mk[(size_t)5 << msh];
        float e0 = __expf(f1.x);
        float e1 = __expf(f1.y);
        unsigned char cm = mk[(size_t)1 << msh];
        __syncwarp();

        // One recurrence step: read src (prev p, packed), write dst (new p).
        auto step = [&](int s, const u64* src, u64* dst) {
            const ulonglong2* q2 = (const ulonglong2*)src;
            // 16 broadcast LDS.128; 64 FFMA2 in 8 straight-line depth-8 chains.
            u64 aA0 = 0ull, aA1 = 0ull, aA2 = 0ull, aA3 = 0ull;
            u64 aB0 = 0ull, aB1 = 0ull, aB2 = 0ull, aB3 = 0ull;
#pragma unroll
            for (int m = 0; m < 16; m += 2) {
                ulonglong2 qa = q2[m];
                ulonglong2 qb = q2[m + 1];
                aA0 = ffma2(EA[2 * m],     qa.x, aA0);
                aB0 = ffma2(EB[2 * m],     qa.x, aB0);
                aA1 = ffma2(EA[2 * m + 1], qa.y, aA1);
                aB1 = ffma2(EB[2 * m + 1], qa.y, aB1);
                aA2 = ffma2(EA[2 * m + 2], qb.x, aA2);
                aB2 = ffma2(EB[2 * m + 2], qb.x, aB2);
                aA3 = ffma2(EA[2 * m + 3], qb.y, aA3);
                aB3 = ffma2(EB[2 * m + 3], qb.y, aB3);
            }

            // FIFO rotate (renamed under the 2x body) + clamped prefetch.
            const float2 head      = f2;
            const unsigned char mh = m2;
            f2 = f3; m2 = m3;
            f3 = f4; m3 = m4;
            f4 = f5; m4 = m5;
            const int sp = (s + 5 < CRF_S) ? (s + 5) : (CRF_S - 1);
            f5 = ((const float2*)(lg + (size_t)sp * CRF_T))[l];
            m5 = mk[(size_t)sp << msh];
            const float ne0 = __expf(head.x);
            const float ne1 = __expf(head.y);

            float2 sA = unpack2(fadd2(fadd2(aA0, aA1), fadd2(aA2, aA3)));
            float2 sB = unpack2(fadd2(fadd2(aB0, aB1), fadd2(aB2, aB3)));
            const float pn0 = (sA.x + sA.y) * e0;
            const float pn1 = (sB.x + sB.y) * e1;
            if (cm) { p0 = pn0; p1 = pn1; }     // mask: keep old alpha if 0

            // Exact power-of-2 renorm every 4 steps: lane-0 exponent broadcast
            // (1 shfl). Scaling is exact; only magnitude containment needed.
            if ((s & 3) == 0) {
                int e = (__float_as_int(p0) >> 23) & 255;
                e = __shfl_sync(0xffffffffu, e, 0);
                float scale = __int_as_float((254 - e) << 23);   // 2^(127-e)
                p0 *= scale;
                p1 *= scale;
                C += (float)(e - 127) * 0.6931471805599453f;
            }

            dst[l] = pack2(p0, p1);
            e0 = ne0; e1 = ne1; cm = mh;
            __syncwarp();
        };

        // s = 1..510 in pairs (static ping-pong), tail s = 511.
        for (int s = 1; s < CRF_S - 1; s += 2) {
            step(s,     psm[w][0], psm[w][1]);
            step(s + 1, psm[w][1], psm[w][0]);
        }
        step(CRF_S - 1, psm[w][0], psm[w][1]);

        // denom = C + log(sum_j p_j * exp(end_j))
        float v = p0 * __expf(endT[j0]) + p1 * __expf(endT[j0 + 1]);
#pragma unroll
        for (int o = 16; o; o >>= 1) v += __shfl_xor_sync(0xffffffffu, v, o);
        if (l == 0) g_dpart[b] = C + logf(v);
    }

    // ---- last CTA performs the final deterministic reduction ----
    __syncthreads();
    if (tid == 0) {
        __threadfence();
        unsigned t = atomicAdd(&g_ticket, 1u);
        do_red = (t == gridDim.x - 1);
    }
    __syncthreads();
    if (do_red) {
        __threadfence();
        float a = 0.0f;
        for (int i = tid; i < CRF_B; i += 160)     // fixed order per thread
            a += g_npart[i] - g_dpart[i];
        rbuf[tid] = a;
        if (tid < 96) rbuf[160 + tid] = 0.0f;
        __syncthreads();
        for (int o = 128; o; o >>= 1) {
            if (tid < o) rbuf[tid] += rbuf[tid + o];
            __syncthreads();
        }
        if (tid == 0) { out[0] = rbuf[0]; g_ticket = 0u; }
    }
}

extern "C" void kernel_launch(void* const* d_in, const int* in_sizes, int n_in,
                              void* d_out, int out_size)
{
    const float* logits = (const float*)d_in[0];
    const void*  tags   = d_in[1];
    const void*  mask   = d_in[2];
    const float* trans  = (const float*)d_in[3];
    const float* startT = (const float*)d_in[4];
    const float* endT   = (const float*)d_in[5];
    float*       out    = (float*)d_out;

    crf_main<<<CRF_B / 4, 160>>>(logits, tags, mask, trans, startT, endT, out);
}